// round 15
// baseline (speedup 1.0000x reference)
#include <cuda_runtime.h>
#include <cuda_fp16.h>
#include <cstdint>

#define N_NODES 100000
#define N_EDGES 3200000
#define IN_DIM  256
#define HIDDEN  128
#define OUT_DIM 64
#define CAP     96      // fixed per-row edge bucket capacity (Poisson(32) tail @96 ~ 1e-18)

typedef unsigned long long ull;

// ---------------- device scratch (static; no cudaMalloc) ----------------
// invariant: g_cnt is all-zero at kernel_launch entry
// (zero-initialized at module load; re-zeroed by spmm2_kernel every call).
__device__ __align__(128) __half g_h0[(size_t)N_NODES * HIDDEN];  // X @ W1 (fp16)
__device__ __align__(128) __half g_h1[(size_t)N_NODES * HIDDEN];  // relu(A @ h0) (fp16)
__device__ __align__(128) __half g_h2[(size_t)N_NODES * OUT_DIM]; // h1 @ W2 (fp16)
__device__ int  g_cnt[N_NODES];
__device__ __align__(128) int2 g_edges[(size_t)N_NODES * CAP];    // bucketed {src, val bits}

// ---------------- helpers ----------------
__device__ __forceinline__ uint32_t smem_u32(const void* p) {
    return (uint32_t)__cvta_generic_to_shared(p);
}
__device__ __forceinline__ void ldmatrix_x4(uint32_t& r0, uint32_t& r1, uint32_t& r2,
                                            uint32_t& r3, uint32_t addr) {
    asm volatile("ldmatrix.sync.aligned.m8n8.x4.shared.b16 {%0,%1,%2,%3}, [%4];"
                 : "=r"(r0), "=r"(r1), "=r"(r2), "=r"(r3) : "r"(addr));
}
__device__ __forceinline__ void ldmatrix_x4_t(uint32_t& r0, uint32_t& r1, uint32_t& r2,
                                              uint32_t& r3, uint32_t addr) {
    asm volatile("ldmatrix.sync.aligned.m8n8.x4.trans.shared.b16 {%0,%1,%2,%3}, [%4];"
                 : "=r"(r0), "=r"(r1), "=r"(r2), "=r"(r3) : "r"(addr));
}
__device__ __forceinline__ void mma16816(float* d, const uint32_t* a, const uint32_t* b) {
    asm volatile("mma.sync.aligned.m16n8k16.row.col.f32.f16.f16.f32 "
                 "{%0,%1,%2,%3}, {%4,%5,%6,%7}, {%8,%9}, {%0,%1,%2,%3};"
                 : "+f"(d[0]), "+f"(d[1]), "+f"(d[2]), "+f"(d[3])
                 : "r"(a[0]), "r"(a[1]), "r"(a[2]), "r"(a[3]), "r"(b[0]), "r"(b[1]));
}
__device__ __forceinline__ uint32_t h2bits(__half2 h) {
    return *reinterpret_cast<uint32_t*>(&h);
}

// ---------------- bucket scatter: the whole CSR build in ONE kernel ----------------
// rank within the row comes from the counting atomic; bucket base = d * CAP.
__global__ void scatter_kernel(const int* __restrict__ edge_src,
                               const int* __restrict__ edge_dst,
                               const float* __restrict__ adj_vals) {
    int e = blockIdx.x * blockDim.x + threadIdx.x;
    if (e >= N_EDGES) return;
    int d = edge_dst[e];
    int rank = atomicAdd(&g_cnt[d], 1);
    if (rank < CAP)
        g_edges[(size_t)d * CAP + rank] = make_int2(edge_src[e], __float_as_int(adj_vals[e]));
}

// ---------------- tensor-core GEMM: C[M,TN] = half(A[M,K] @ B_f32[K,TN]) ----------------
template<int K_DIM, int TN, bool A_IS_F32>
__global__ __launch_bounds__(256)
void gemm_tc_kernel(const void* __restrict__ Ain, const float* __restrict__ Bf,
                    __half* __restrict__ C, int M) {
    extern __shared__ __half sm[];
    constexpr int AP = K_DIM + 8;
    constexpr int BP = TN + 8;
    __half* As = sm;                       // [128][AP]
    __half* Bs = sm + 128 * AP;            // [K_DIM][BP]

    const int t = threadIdx.x;
    const int row0 = blockIdx.x * 128;

    #pragma unroll
    for (int i = t; i < K_DIM * TN / 4; i += 256) {
        int k  = i / (TN / 4);
        int n4 = i % (TN / 4);
        float4 v = __ldg((const float4*)(Bf + (size_t)k * TN + n4 * 4));
        uint2 o = make_uint2(h2bits(__floats2half2_rn(v.x, v.y)),
                             h2bits(__floats2half2_rn(v.z, v.w)));
        *reinterpret_cast<uint2*>(Bs + k * BP + n4 * 4) = o;
    }
    if (A_IS_F32) {
        const float* A = (const float*)Ain;
        #pragma unroll
        for (int i = t; i < 128 * K_DIM / 4; i += 256) {
            int m  = i / (K_DIM / 4);
            int k4 = i % (K_DIM / 4);
            int gr = row0 + m;
            float4 v = make_float4(0.f, 0.f, 0.f, 0.f);
            if (gr < M) v = __ldg((const float4*)(A + (size_t)gr * K_DIM + k4 * 4));
            uint2 o = make_uint2(h2bits(__floats2half2_rn(v.x, v.y)),
                                 h2bits(__floats2half2_rn(v.z, v.w)));
            *reinterpret_cast<uint2*>(As + m * AP + k4 * 4) = o;
        }
    } else {
        const __half* A = (const __half*)Ain;
        #pragma unroll
        for (int i = t; i < 128 * K_DIM / 8; i += 256) {
            int m  = i / (K_DIM / 8);
            int k8 = i % (K_DIM / 8);
            int gr = row0 + m;
            uint4 v = make_uint4(0u, 0u, 0u, 0u);
            if (gr < M) v = __ldg((const uint4*)(A + (size_t)gr * K_DIM + k8 * 8));
            *reinterpret_cast<uint4*>(As + m * AP + k8 * 8) = v;
        }
    }
    __syncthreads();

    const int wid  = t >> 5;
    const int lane = t & 31;
    const int wm = wid & 3;
    const int wn = wid >> 2;
    const int m_base = wm * 32;
    const int n_base = wn * (TN / 2);
    constexpr int NTILES = TN / 2 / 8;

    float acc[2][NTILES][4];
    #pragma unroll
    for (int i = 0; i < 2; ++i)
        #pragma unroll
        for (int j = 0; j < NTILES; ++j)
            #pragma unroll
            for (int q = 0; q < 4; ++q) acc[i][j][q] = 0.f;

    const int a_row_off = lane & 15;
    const int a_col_off = (lane >> 4) * 8;
    const int b_krow = (lane & 7) + ((lane >> 3) & 1) * 8;
    const int b_ncol = (lane >> 4) * 8;

    #pragma unroll
    for (int ks = 0; ks < K_DIM / 16; ++ks) {
        const int k0 = ks * 16;
        uint32_t afrag[2][4];
        #pragma unroll
        for (int i = 0; i < 2; ++i) {
            int r = m_base + i * 16 + a_row_off;
            uint32_t addr = smem_u32(As + r * AP + k0 + a_col_off);
            ldmatrix_x4(afrag[i][0], afrag[i][1], afrag[i][2], afrag[i][3], addr);
        }
        uint32_t bfrag[NTILES][2];
        #pragma unroll
        for (int j = 0; j < NTILES / 2; ++j) {
            int kr = k0 + b_krow;
            int nc = n_base + j * 16 + b_ncol;
            uint32_t addr = smem_u32(Bs + kr * BP + nc);
            ldmatrix_x4_t(bfrag[2 * j][0], bfrag[2 * j][1],
                          bfrag[2 * j + 1][0], bfrag[2 * j + 1][1], addr);
        }
        #pragma unroll
        for (int i = 0; i < 2; ++i)
            #pragma unroll
            for (int j = 0; j < NTILES; ++j)
                mma16816(acc[i][j], afrag[i], bfrag[j]);
    }

    const int erow = lane >> 2;
    const int ecol = (lane & 3) * 2;
    #pragma unroll
    for (int i = 0; i < 2; ++i) {
        int r0 = row0 + m_base + i * 16 + erow;
        #pragma unroll
        for (int j = 0; j < NTILES; ++j) {
            int col = n_base + j * 8 + ecol;
            if (r0 < M) {
                __half2 h = __floats2half2_rn(acc[i][j][0], acc[i][j][1]);
                *reinterpret_cast<uint32_t*>(C + (size_t)r0 * TN + col) = h2bits(h);
            }
            if (r0 + 8 < M) {
                __half2 h = __floats2half2_rn(acc[i][j][2], acc[i][j][3]);
                *reinterpret_cast<uint32_t*>(C + (size_t)(r0 + 8) * TN + col) = h2bits(h);
            }
        }
    }
}

// ---------------- spmm1: h1 = relu(A @ h0_fp16), fp16 out; warp-per-row ----------------
// Paired broadcast int4 edge loads (two edges each); bucket base row*CAP is 16B-aligned.
__global__ void spmm1_relu_kernel(const __half* __restrict__ h0, __half* __restrict__ h1) {
    int row = (int)((blockIdx.x * blockDim.x + threadIdx.x) >> 5);
    if (row >= N_NODES) return;
    int lane = threadIdx.x & 31;
    int len = g_cnt[row]; if (len > CAP) len = CAP;
    const int2* __restrict__ ebase = g_edges + (size_t)row * CAP;
    int c = lane * 4;
    float4 acc = make_float4(0.f, 0.f, 0.f, 0.f);

    int e = 0;
    for (; e + 3 < len; e += 4) {
        int4 p0 = __ldg((const int4*)(ebase + e));       // edges e, e+1
        int4 p1 = __ldg((const int4*)(ebase + e + 2));   // edges e+2, e+3
        uint2 r0 = __ldg((const uint2*)(h0 + ((size_t)p0.x << 7) + c));
        uint2 r1 = __ldg((const uint2*)(h0 + ((size_t)p0.z << 7) + c));
        uint2 r2 = __ldg((const uint2*)(h0 + ((size_t)p1.x << 7) + c));
        uint2 r3 = __ldg((const uint2*)(h0 + ((size_t)p1.z << 7) + c));
        float v0 = __int_as_float(p0.y), v1 = __int_as_float(p0.w);
        float v2 = __int_as_float(p1.y), v3 = __int_as_float(p1.w);
        float2 a0 = __half22float2(*reinterpret_cast<__half2*>(&r0.x));
        float2 b0 = __half22float2(*reinterpret_cast<__half2*>(&r0.y));
        float2 a1 = __half22float2(*reinterpret_cast<__half2*>(&r1.x));
        float2 b1 = __half22float2(*reinterpret_cast<__half2*>(&r1.y));
        float2 a2 = __half22float2(*reinterpret_cast<__half2*>(&r2.x));
        float2 b2 = __half22float2(*reinterpret_cast<__half2*>(&r2.y));
        float2 a3 = __half22float2(*reinterpret_cast<__half2*>(&r3.x));
        float2 b3 = __half22float2(*reinterpret_cast<__half2*>(&r3.y));
        acc.x = fmaf(v0, a0.x, acc.x); acc.y = fmaf(v0, a0.y, acc.y);
        acc.z = fmaf(v0, b0.x, acc.z); acc.w = fmaf(v0, b0.y, acc.w);
        acc.x = fmaf(v1, a1.x, acc.x); acc.y = fmaf(v1, a1.y, acc.y);
        acc.z = fmaf(v1, b1.x, acc.z); acc.w = fmaf(v1, b1.y, acc.w);
        acc.x = fmaf(v2, a2.x, acc.x); acc.y = fmaf(v2, a2.y, acc.y);
        acc.z = fmaf(v2, b2.x, acc.z); acc.w = fmaf(v2, b2.y, acc.w);
        acc.x = fmaf(v3, a3.x, acc.x); acc.y = fmaf(v3, a3.y, acc.y);
        acc.z = fmaf(v3, b3.x, acc.z); acc.w = fmaf(v3, b3.y, acc.w);
    }
    for (; e < len; ++e) {
        int2 d0 = __ldg(ebase + e);
        float v0 = __int_as_float(d0.y);
        uint2 r0 = __ldg((const uint2*)(h0 + ((size_t)d0.x << 7) + c));
        float2 a0 = __half22float2(*reinterpret_cast<__half2*>(&r0.x));
        float2 b0 = __half22float2(*reinterpret_cast<__half2*>(&r0.y));
        acc.x = fmaf(v0, a0.x, acc.x); acc.y = fmaf(v0, a0.y, acc.y);
        acc.z = fmaf(v0, b0.x, acc.z); acc.w = fmaf(v0, b0.y, acc.w);
    }
    __half2 o0 = __floats2half2_rn(fmaxf(acc.x, 0.f), fmaxf(acc.y, 0.f));
    __half2 o1 = __floats2half2_rn(fmaxf(acc.z, 0.f), fmaxf(acc.w, 0.f));
    uint2 ov = make_uint2(h2bits(o0), h2bits(o1));
    *reinterpret_cast<uint2*>(h1 + ((size_t)row << 7) + c) = ov;
}

// ---------------- spmm2: out = A @ h2_fp16 (fp32 out); half-warp per row ----------------
// Also restores the zero-invariant on g_cnt (last consumer of the counts).
__global__ void spmm2_kernel(const __half* __restrict__ h2, float* __restrict__ out) {
    int gt = blockIdx.x * blockDim.x + threadIdx.x;
    int row = gt >> 4;
    if (row >= N_NODES) return;
    int lane16 = threadIdx.x & 15;
    int len = g_cnt[row]; if (len > CAP) len = CAP;
    if (lane16 == 0) g_cnt[row] = 0;   // restore invariant for next launch
    const int2* __restrict__ ebase = g_edges + (size_t)row * CAP;
    int c = lane16 * 4;
    float4 acc = make_float4(0.f, 0.f, 0.f, 0.f);

    int e = 0;
    for (; e + 3 < len; e += 4) {
        int4 p0 = __ldg((const int4*)(ebase + e));
        int4 p1 = __ldg((const int4*)(ebase + e + 2));
        uint2 r0 = __ldg((const uint2*)(h2 + ((size_t)p0.x << 6) + c));
        uint2 r1 = __ldg((const uint2*)(h2 + ((size_t)p0.z << 6) + c));
        uint2 r2 = __ldg((const uint2*)(h2 + ((size_t)p1.x << 6) + c));
        uint2 r3 = __ldg((const uint2*)(h2 + ((size_t)p1.z << 6) + c));
        float v0 = __int_as_float(p0.y), v1 = __int_as_float(p0.w);
        float v2 = __int_as_float(p1.y), v3 = __int_as_float(p1.w);
        float2 a0 = __half22float2(*reinterpret_cast<__half2*>(&r0.x));
        float2 b0 = __half22float2(*reinterpret_cast<__half2*>(&r0.y));
        float2 a1 = __half22float2(*reinterpret_cast<__half2*>(&r1.x));
        float2 b1 = __half22float2(*reinterpret_cast<__half2*>(&r1.y));
        float2 a2 = __half22float2(*reinterpret_cast<__half2*>(&r2.x));
        float2 b2 = __half22float2(*reinterpret_cast<__half2*>(&r2.y));
        float2 a3 = __half22float2(*reinterpret_cast<__half2*>(&r3.x));
        float2 b3 = __half22float2(*reinterpret_cast<__half2*>(&r3.y));
        acc.x = fmaf(v0, a0.x, acc.x); acc.y = fmaf(v0, a0.y, acc.y);
        acc.z = fmaf(v0, b0.x, acc.z); acc.w = fmaf(v0, b0.y, acc.w);
        acc.x = fmaf(v1, a1.x, acc.x); acc.y = fmaf(v1, a1.y, acc.y);
        acc.z = fmaf(v1, b1.x, acc.z); acc.w = fmaf(v1, b1.y, acc.w);
        acc.x = fmaf(v2, a2.x, acc.x); acc.y = fmaf(v2, a2.y, acc.y);
        acc.z = fmaf(v2, b2.x, acc.z); acc.w = fmaf(v2, b2.y, acc.w);
        acc.x = fmaf(v3, a3.x, acc.x); acc.y = fmaf(v3, a3.y, acc.y);
        acc.z = fmaf(v3, b3.x, acc.z); acc.w = fmaf(v3, b3.y, acc.w);
    }
    for (; e < len; ++e) {
        int2 d0 = __ldg(ebase + e);
        float v0 = __int_as_float(d0.y);
        uint2 r0 = __ldg((const uint2*)(h2 + ((size_t)d0.x << 6) + c));
        float2 a0 = __half22float2(*reinterpret_cast<__half2*>(&r0.x));
        float2 b0 = __half22float2(*reinterpret_cast<__half2*>(&r0.y));
        acc.x = fmaf(v0, a0.x, acc.x); acc.y = fmaf(v0, a0.y, acc.y);
        acc.z = fmaf(v0, b0.x, acc.z); acc.w = fmaf(v0, b0.y, acc.w);
    }
    *reinterpret_cast<float4*>(out + ((size_t)row << 6) + c) = acc;
}

// ---------------- launch ----------------
extern "C" void kernel_launch(void* const* d_in, const int* in_sizes, int n_in,
                              void* d_out, int out_size) {
    const float* x        = (const float*)d_in[0];
    const float* adj_vals = (const float*)d_in[1];
    const float* w1       = (const float*)d_in[2];
    const float* w2       = (const float*)d_in[3];
    const int*   edge_src = (const int*)d_in[4];
    const int*   edge_dst = (const int*)d_in[5];
    float* out = (float*)d_out;

    __half *p_h0, *p_h1, *p_h2;
    cudaGetSymbolAddress((void**)&p_h0, g_h0);
    cudaGetSymbolAddress((void**)&p_h1, g_h1);
    cudaGetSymbolAddress((void**)&p_h2, g_h2);

    const int TPB = 256;

    const int SMEM1 = (128 * (IN_DIM + 8) + IN_DIM * (HIDDEN + 8)) * (int)sizeof(__half);
    const int SMEM2 = (128 * (HIDDEN + 8) + HIDDEN * (OUT_DIM + 8)) * (int)sizeof(__half);
    cudaFuncSetAttribute(gemm_tc_kernel<IN_DIM, HIDDEN, true>,
                         cudaFuncAttributeMaxDynamicSharedMemorySize, SMEM1);
    cudaFuncSetAttribute(gemm_tc_kernel<HIDDEN, OUT_DIM, false>,
                         cudaFuncAttributeMaxDynamicSharedMemorySize, SMEM2);

    const int GBLK = (N_NODES + 127) / 128;

    // Fork: gemm1 (x,w1 only) on a side stream; bucket scatter on the main stream.
    cudaStream_t s2;
    cudaEvent_t evFork, evJoin;
    cudaStreamCreateWithFlags(&s2, cudaStreamNonBlocking);
    cudaEventCreateWithFlags(&evFork, cudaEventDisableTiming);
    cudaEventCreateWithFlags(&evJoin, cudaEventDisableTiming);

    cudaEventRecord(evFork, 0);
    cudaStreamWaitEvent(s2, evFork, 0);
    gemm_tc_kernel<IN_DIM, HIDDEN, true><<<GBLK, 256, SMEM1, s2>>>(x, w1, p_h0, N_NODES);
    cudaEventRecord(evJoin, s2);

    // Edge bucketing: ONE kernel (g_cnt is zero on entry; spmm2 re-zeroes it).
    scatter_kernel<<<(N_EDGES + TPB - 1) / TPB, TPB>>>(edge_src, edge_dst, adj_vals);

    cudaStreamWaitEvent(0, evJoin, 0);

    // h1 = half(relu(A @ h0))
    spmm1_relu_kernel<<<(N_NODES * 32 + TPB - 1) / TPB, TPB>>>(p_h0, p_h1);
    // layer 2: h2 = half(h1 @ W2)
    gemm_tc_kernel<HIDDEN, OUT_DIM, false><<<GBLK, 256, SMEM2>>>(p_h1, w2, p_h2, N_NODES);
    // out = A @ h2 (also restores g_cnt zero-invariant)
    spmm2_kernel<<<(N_NODES * 16 + TPB - 1) / TPB, TPB>>>(p_h2, out);

    cudaStreamCaptureStatus cap = cudaStreamCaptureStatusNone;
    cudaStreamIsCapturing(0, &cap);
    if (cap == cudaStreamCaptureStatusNone) {
        cudaStreamDestroy(s2);
        cudaEventDestroy(evFork);
        cudaEventDestroy(evJoin);
    }
}

// round 16
// speedup vs baseline: 1.2943x; 1.2943x over previous
#include <cuda_runtime.h>
#include <cuda_fp16.h>
#include <cstdint>

#define N_NODES 100000
#define N_EDGES 3200000
#define IN_DIM  256
#define HIDDEN  128
#define OUT_DIM 64

typedef unsigned long long ull;

#define SCAN_BLOCKS 98

// ---------------- device scratch (static; no cudaMalloc) ----------------
// invariant: g_cnt and g_scan_state are all-zero at kernel_launch entry
// (zero-initialized at module load; re-zeroed by scatter_kernel every call).
__device__ __align__(128) __half g_h0[(size_t)N_NODES * HIDDEN];  // X @ W1 (fp16)
__device__ __align__(128) __half g_h1[(size_t)N_NODES * HIDDEN];  // relu(A @ h0) (fp16)
__device__ __align__(128) __half g_h2[(size_t)N_NODES * OUT_DIM]; // h1 @ W2 (fp16)
__device__ int  g_cnt[N_NODES];
__device__ int  g_row_ptr[N_NODES + 1];
__device__ int  g_cursor[N_NODES];
__device__ ull  g_scan_state[SCAN_BLOCKS];                        // (sum<<2)|flag
__device__ __align__(128) int2 g_edges[N_EDGES];                  // {src, val bits}

// ---------------- helpers ----------------
__device__ __forceinline__ uint32_t smem_u32(const void* p) {
    return (uint32_t)__cvta_generic_to_shared(p);
}
__device__ __forceinline__ void ldmatrix_x4(uint32_t& r0, uint32_t& r1, uint32_t& r2,
                                            uint32_t& r3, uint32_t addr) {
    asm volatile("ldmatrix.sync.aligned.m8n8.x4.shared.b16 {%0,%1,%2,%3}, [%4];"
                 : "=r"(r0), "=r"(r1), "=r"(r2), "=r"(r3) : "r"(addr));
}
__device__ __forceinline__ void ldmatrix_x4_t(uint32_t& r0, uint32_t& r1, uint32_t& r2,
                                              uint32_t& r3, uint32_t addr) {
    asm volatile("ldmatrix.sync.aligned.m8n8.x4.trans.shared.b16 {%0,%1,%2,%3}, [%4];"
                 : "=r"(r0), "=r"(r1), "=r"(r2), "=r"(r3) : "r"(addr));
}
__device__ __forceinline__ void mma16816(float* d, const uint32_t* a, const uint32_t* b) {
    asm volatile("mma.sync.aligned.m16n8k16.row.col.f32.f16.f16.f32 "
                 "{%0,%1,%2,%3}, {%4,%5,%6,%7}, {%8,%9}, {%0,%1,%2,%3};"
                 : "+f"(d[0]), "+f"(d[1]), "+f"(d[2]), "+f"(d[3])
                 : "r"(a[0]), "r"(a[1]), "r"(a[2]), "r"(a[3]), "r"(b[0]), "r"(b[1]));
}
__device__ __forceinline__ uint32_t h2bits(__half2 h) {
    return *reinterpret_cast<uint32_t*>(&h);
}

// ---------------- CSR build ----------------
__global__ void hist_kernel(const int* __restrict__ edge_dst) {
    int e = blockIdx.x * blockDim.x + threadIdx.x;
    if (e < N_EDGES) atomicAdd(&g_cnt[edge_dst[e]], 1);
}

__device__ __forceinline__ int warp_incl_scan(int v) {
    int lane = threadIdx.x & 31;
    #pragma unroll
    for (int o = 1; o < 32; o <<= 1) {
        int n = __shfl_up_sync(0xffffffffu, v, o);
        if (lane >= o) v += n;
    }
    return v;
}

// single-pass decoupled-lookback exclusive scan: g_cnt -> g_row_ptr, g_cursor
__global__ __launch_bounds__(1024)
void scan_lookback_kernel() {
    __shared__ int ws[32];
    __shared__ int s_prefix;
    const int bid = blockIdx.x;
    const int i = bid * 1024 + threadIdx.x;
    int v = (i < N_NODES) ? g_cnt[i] : 0;
    int incl = warp_incl_scan(v);
    int wid = threadIdx.x >> 5, lane = threadIdx.x & 31;
    if (lane == 31) ws[wid] = incl;
    __syncthreads();
    if (wid == 0) { int w = warp_incl_scan(ws[lane]); ws[lane] = w; }
    __syncthreads();
    int woff = (wid > 0) ? ws[wid - 1] : 0;
    int btotal = ws[31];

    if (threadIdx.x == 0) {
        ull pack = ((ull)(uint32_t)btotal << 2) | (bid == 0 ? 2u : 1u);
        atomicExch(&g_scan_state[bid], pack);
        int run = 0;
        if (bid > 0) {
            int idx = bid - 1;
            while (true) {
                ull s = atomicAdd(&g_scan_state[idx], 0ull);
                uint32_t flag = (uint32_t)(s & 3ull);
                if (flag == 0u) continue;
                run += (int)(s >> 2);
                if (flag == 2u) break;
                --idx;
            }
            atomicExch(&g_scan_state[bid],
                       ((ull)(uint32_t)(run + btotal) << 2) | 2u);
        }
        s_prefix = run;
    }
    __syncthreads();

    int ex = s_prefix + woff + incl - v;
    if (i < N_NODES) {
        g_row_ptr[i] = ex;
        g_cursor[i]  = ex;
    }
    if (bid == SCAN_BLOCKS - 1 && threadIdx.x == 1023)
        g_row_ptr[N_NODES] = N_EDGES;
}

// scatter (1 edge/thread) + restore zero-invariant on g_cnt / g_scan_state
__global__ void scatter_kernel(const int* __restrict__ edge_src,
                               const int* __restrict__ edge_dst,
                               const float* __restrict__ adj_vals) {
    int e = blockIdx.x * blockDim.x + threadIdx.x;
    if (e < N_NODES) g_cnt[e] = 0;
    if (e < SCAN_BLOCKS) g_scan_state[e] = 0ull;
    if (e >= N_EDGES) return;
    int d = edge_dst[e];
    int pos = atomicAdd(&g_cursor[d], 1);
    g_edges[pos] = make_int2(edge_src[e], __float_as_int(adj_vals[e]));
}

// ---------------- tensor-core GEMM: C[M,TN] = half(A[M,K] @ B_f32[K,TN]) ----------------
template<int K_DIM, int TN, bool A_IS_F32>
__global__ __launch_bounds__(256)
void gemm_tc_kernel(const void* __restrict__ Ain, const float* __restrict__ Bf,
                    __half* __restrict__ C, int M) {
    extern __shared__ __half sm[];
    constexpr int AP = K_DIM + 8;
    constexpr int BP = TN + 8;
    __half* As = sm;                       // [128][AP]
    __half* Bs = sm + 128 * AP;            // [K_DIM][BP]

    const int t = threadIdx.x;
    const int row0 = blockIdx.x * 128;

    #pragma unroll
    for (int i = t; i < K_DIM * TN / 4; i += 256) {
        int k  = i / (TN / 4);
        int n4 = i % (TN / 4);
        float4 v = __ldg((const float4*)(Bf + (size_t)k * TN + n4 * 4));
        uint2 o = make_uint2(h2bits(__floats2half2_rn(v.x, v.y)),
                             h2bits(__floats2half2_rn(v.z, v.w)));
        *reinterpret_cast<uint2*>(Bs + k * BP + n4 * 4) = o;
    }
    if (A_IS_F32) {
        const float* A = (const float*)Ain;
        #pragma unroll
        for (int i = t; i < 128 * K_DIM / 4; i += 256) {
            int m  = i / (K_DIM / 4);
            int k4 = i % (K_DIM / 4);
            int gr = row0 + m;
            float4 v = make_float4(0.f, 0.f, 0.f, 0.f);
            if (gr < M) v = __ldg((const float4*)(A + (size_t)gr * K_DIM + k4 * 4));
            uint2 o = make_uint2(h2bits(__floats2half2_rn(v.x, v.y)),
                                 h2bits(__floats2half2_rn(v.z, v.w)));
            *reinterpret_cast<uint2*>(As + m * AP + k4 * 4) = o;
        }
    } else {
        const __half* A = (const __half*)Ain;
        #pragma unroll
        for (int i = t; i < 128 * K_DIM / 8; i += 256) {
            int m  = i / (K_DIM / 8);
            int k8 = i % (K_DIM / 8);
            int gr = row0 + m;
            uint4 v = make_uint4(0u, 0u, 0u, 0u);
            if (gr < M) v = __ldg((const uint4*)(A + (size_t)gr * K_DIM + k8 * 8));
            *reinterpret_cast<uint4*>(As + m * AP + k8 * 8) = v;
        }
    }
    __syncthreads();

    const int wid  = t >> 5;
    const int lane = t & 31;
    const int wm = wid & 3;
    const int wn = wid >> 2;
    const int m_base = wm * 32;
    const int n_base = wn * (TN / 2);
    constexpr int NTILES = TN / 2 / 8;

    float acc[2][NTILES][4];
    #pragma unroll
    for (int i = 0; i < 2; ++i)
        #pragma unroll
        for (int j = 0; j < NTILES; ++j)
            #pragma unroll
            for (int q = 0; q < 4; ++q) acc[i][j][q] = 0.f;

    const int a_row_off = lane & 15;
    const int a_col_off = (lane >> 4) * 8;
    const int b_krow = (lane & 7) + ((lane >> 3) & 1) * 8;
    const int b_ncol = (lane >> 4) * 8;

    #pragma unroll
    for (int ks = 0; ks < K_DIM / 16; ++ks) {
        const int k0 = ks * 16;
        uint32_t afrag[2][4];
        #pragma unroll
        for (int i = 0; i < 2; ++i) {
            int r = m_base + i * 16 + a_row_off;
            uint32_t addr = smem_u32(As + r * AP + k0 + a_col_off);
            ldmatrix_x4(afrag[i][0], afrag[i][1], afrag[i][2], afrag[i][3], addr);
        }
        uint32_t bfrag[NTILES][2];
        #pragma unroll
        for (int j = 0; j < NTILES / 2; ++j) {
            int kr = k0 + b_krow;
            int nc = n_base + j * 16 + b_ncol;
            uint32_t addr = smem_u32(Bs + kr * BP + nc);
            ldmatrix_x4_t(bfrag[2 * j][0], bfrag[2 * j][1],
                          bfrag[2 * j + 1][0], bfrag[2 * j + 1][1], addr);
        }
        #pragma unroll
        for (int i = 0; i < 2; ++i)
            #pragma unroll
            for (int j = 0; j < NTILES; ++j)
                mma16816(acc[i][j], afrag[i], bfrag[j]);
    }

    const int erow = lane >> 2;
    const int ecol = (lane & 3) * 2;
    #pragma unroll
    for (int i = 0; i < 2; ++i) {
        int r0 = row0 + m_base + i * 16 + erow;
        #pragma unroll
        for (int j = 0; j < NTILES; ++j) {
            int col = n_base + j * 8 + ecol;
            if (r0 < M) {
                __half2 h = __floats2half2_rn(acc[i][j][0], acc[i][j][1]);
                *reinterpret_cast<uint32_t*>(C + (size_t)r0 * TN + col) = h2bits(h);
            }
            if (r0 + 8 < M) {
                __half2 h = __floats2half2_rn(acc[i][j][2], acc[i][j][3]);
                *reinterpret_cast<uint32_t*>(C + (size_t)(r0 + 8) * TN + col) = h2bits(h);
            }
        }
    }
}

// ---------------- spmm1: h1 = relu(A @ h0_fp16), fp16 out; warp-per-row ----------------
// Paired edge loads: one broadcast int4 = two edges (halves edge-load wavefronts).
__global__ void spmm1_relu_kernel(const __half* __restrict__ h0, __half* __restrict__ h1) {
    int row = (int)((blockIdx.x * blockDim.x + threadIdx.x) >> 5);
    if (row >= N_NODES) return;
    int lane = threadIdx.x & 31;
    int beg = g_row_ptr[row];
    int end = g_row_ptr[row + 1];
    int c = lane * 4;
    float4 acc = make_float4(0.f, 0.f, 0.f, 0.f);

    int e = beg;
    // align to even index so int4 (16B) paired loads are aligned
    if ((e & 1) && e < end) {
        int2 d0 = __ldg(&g_edges[e]);
        float v0 = __int_as_float(d0.y);
        uint2 r0 = __ldg((const uint2*)(h0 + ((size_t)d0.x << 7) + c));
        float2 a0 = __half22float2(*reinterpret_cast<__half2*>(&r0.x));
        float2 b0 = __half22float2(*reinterpret_cast<__half2*>(&r0.y));
        acc.x = fmaf(v0, a0.x, acc.x); acc.y = fmaf(v0, a0.y, acc.y);
        acc.z = fmaf(v0, b0.x, acc.z); acc.w = fmaf(v0, b0.y, acc.w);
        ++e;
    }
    // 2 pairs (4 edges) per iteration
    for (; e + 3 < end; e += 4) {
        int4 p0 = __ldg((const int4*)(g_edges + e));       // edges e, e+1
        int4 p1 = __ldg((const int4*)(g_edges + e + 2));   // edges e+2, e+3
        uint2 r0 = __ldg((const uint2*)(h0 + ((size_t)p0.x << 7) + c));
        uint2 r1 = __ldg((const uint2*)(h0 + ((size_t)p0.z << 7) + c));
        uint2 r2 = __ldg((const uint2*)(h0 + ((size_t)p1.x << 7) + c));
        uint2 r3 = __ldg((const uint2*)(h0 + ((size_t)p1.z << 7) + c));
        float v0 = __int_as_float(p0.y), v1 = __int_as_float(p0.w);
        float v2 = __int_as_float(p1.y), v3 = __int_as_float(p1.w);
        float2 a0 = __half22float2(*reinterpret_cast<__half2*>(&r0.x));
        float2 b0 = __half22float2(*reinterpret_cast<__half2*>(&r0.y));
        float2 a1 = __half22float2(*reinterpret_cast<__half2*>(&r1.x));
        float2 b1 = __half22float2(*reinterpret_cast<__half2*>(&r1.y));
        float2 a2 = __half22float2(*reinterpret_cast<__half2*>(&r2.x));
        float2 b2 = __half22float2(*reinterpret_cast<__half2*>(&r2.y));
        float2 a3 = __half22float2(*reinterpret_cast<__half2*>(&r3.x));
        float2 b3 = __half22float2(*reinterpret_cast<__half2*>(&r3.y));
        acc.x = fmaf(v0, a0.x, acc.x); acc.y = fmaf(v0, a0.y, acc.y);
        acc.z = fmaf(v0, b0.x, acc.z); acc.w = fmaf(v0, b0.y, acc.w);
        acc.x = fmaf(v1, a1.x, acc.x); acc.y = fmaf(v1, a1.y, acc.y);
        acc.z = fmaf(v1, b1.x, acc.z); acc.w = fmaf(v1, b1.y, acc.w);
        acc.x = fmaf(v2, a2.x, acc.x); acc.y = fmaf(v2, a2.y, acc.y);
        acc.z = fmaf(v2, b2.x, acc.z); acc.w = fmaf(v2, b2.y, acc.w);
        acc.x = fmaf(v3, a3.x, acc.x); acc.y = fmaf(v3, a3.y, acc.y);
        acc.z = fmaf(v3, b3.x, acc.z); acc.w = fmaf(v3, b3.y, acc.w);
    }
    for (; e < end; ++e) {
        int2 d0 = __ldg(&g_edges[e]);
        float v0 = __int_as_float(d0.y);
        uint2 r0 = __ldg((const uint2*)(h0 + ((size_t)d0.x << 7) + c));
        float2 a0 = __half22float2(*reinterpret_cast<__half2*>(&r0.x));
        float2 b0 = __half22float2(*reinterpret_cast<__half2*>(&r0.y));
        acc.x = fmaf(v0, a0.x, acc.x); acc.y = fmaf(v0, a0.y, acc.y);
        acc.z = fmaf(v0, b0.x, acc.z); acc.w = fmaf(v0, b0.y, acc.w);
    }
    __half2 o0 = __floats2half2_rn(fmaxf(acc.x, 0.f), fmaxf(acc.y, 0.f));
    __half2 o1 = __floats2half2_rn(fmaxf(acc.z, 0.f), fmaxf(acc.w, 0.f));
    uint2 ov = make_uint2(h2bits(o0), h2bits(o1));
    *reinterpret_cast<uint2*>(h1 + ((size_t)row << 7) + c) = ov;
}

// ---------------- spmm2: out = A @ h2_fp16 (fp32 out); half-warp per row ----------------
// Paired edge loads, same pattern as spmm1.
__global__ void spmm2_kernel(const __half* __restrict__ h2, float* __restrict__ out) {
    int gt = blockIdx.x * blockDim.x + threadIdx.x;
    int row = gt >> 4;
    if (row >= N_NODES) return;
    int lane16 = threadIdx.x & 15;
    int beg = g_row_ptr[row];
    int end = g_row_ptr[row + 1];
    int c = lane16 * 4;
    float4 acc = make_float4(0.f, 0.f, 0.f, 0.f);

    int e = beg;
    if ((e & 1) && e < end) {
        int2 d0 = __ldg(&g_edges[e]);
        float v0 = __int_as_float(d0.y);
        uint2 r0 = __ldg((const uint2*)(h2 + ((size_t)d0.x << 6) + c));
        float2 a0 = __half22float2(*reinterpret_cast<__half2*>(&r0.x));
        float2 b0 = __half22float2(*reinterpret_cast<__half2*>(&r0.y));
        acc.x = fmaf(v0, a0.x, acc.x); acc.y = fmaf(v0, a0.y, acc.y);
        acc.z = fmaf(v0, b0.x, acc.z); acc.w = fmaf(v0, b0.y, acc.w);
        ++e;
    }
    for (; e + 3 < end; e += 4) {
        int4 p0 = __ldg((const int4*)(g_edges + e));
        int4 p1 = __ldg((const int4*)(g_edges + e + 2));
        uint2 r0 = __ldg((const uint2*)(h2 + ((size_t)p0.x << 6) + c));
        uint2 r1 = __ldg((const uint2*)(h2 + ((size_t)p0.z << 6) + c));
        uint2 r2 = __ldg((const uint2*)(h2 + ((size_t)p1.x << 6) + c));
        uint2 r3 = __ldg((const uint2*)(h2 + ((size_t)p1.z << 6) + c));
        float v0 = __int_as_float(p0.y), v1 = __int_as_float(p0.w);
        float v2 = __int_as_float(p1.y), v3 = __int_as_float(p1.w);
        float2 a0 = __half22float2(*reinterpret_cast<__half2*>(&r0.x));
        float2 b0 = __half22float2(*reinterpret_cast<__half2*>(&r0.y));
        float2 a1 = __half22float2(*reinterpret_cast<__half2*>(&r1.x));
        float2 b1 = __half22float2(*reinterpret_cast<__half2*>(&r1.y));
        float2 a2 = __half22float2(*reinterpret_cast<__half2*>(&r2.x));
        float2 b2 = __half22float2(*reinterpret_cast<__half2*>(&r2.y));
        float2 a3 = __half22float2(*reinterpret_cast<__half2*>(&r3.x));
        float2 b3 = __half22float2(*reinterpret_cast<__half2*>(&r3.y));
        acc.x = fmaf(v0, a0.x, acc.x); acc.y = fmaf(v0, a0.y, acc.y);
        acc.z = fmaf(v0, b0.x, acc.z); acc.w = fmaf(v0, b0.y, acc.w);
        acc.x = fmaf(v1, a1.x, acc.x); acc.y = fmaf(v1, a1.y, acc.y);
        acc.z = fmaf(v1, b1.x, acc.z); acc.w = fmaf(v1, b1.y, acc.w);
        acc.x = fmaf(v2, a2.x, acc.x); acc.y = fmaf(v2, a2.y, acc.y);
        acc.z = fmaf(v2, b2.x, acc.z); acc.w = fmaf(v2, b2.y, acc.w);
        acc.x = fmaf(v3, a3.x, acc.x); acc.y = fmaf(v3, a3.y, acc.y);
        acc.z = fmaf(v3, b3.x, acc.z); acc.w = fmaf(v3, b3.y, acc.w);
    }
    for (; e < end; ++e) {
        int2 d0 = __ldg(&g_edges[e]);
        float v0 = __int_as_float(d0.y);
        uint2 r0 = __ldg((const uint2*)(h2 + ((size_t)d0.x << 6) + c));
        float2 a0 = __half22float2(*reinterpret_cast<__half2*>(&r0.x));
        float2 b0 = __half22float2(*reinterpret_cast<__half2*>(&r0.y));
        acc.x = fmaf(v0, a0.x, acc.x); acc.y = fmaf(v0, a0.y, acc.y);
        acc.z = fmaf(v0, b0.x, acc.z); acc.w = fmaf(v0, b0.y, acc.w);
    }
    *reinterpret_cast<float4*>(out + ((size_t)row << 6) + c) = acc;
}

// ---------------- launch ----------------
extern "C" void kernel_launch(void* const* d_in, const int* in_sizes, int n_in,
                              void* d_out, int out_size) {
    const float* x        = (const float*)d_in[0];
    const float* adj_vals = (const float*)d_in[1];
    const float* w1       = (const float*)d_in[2];
    const float* w2       = (const float*)d_in[3];
    const int*   edge_src = (const int*)d_in[4];
    const int*   edge_dst = (const int*)d_in[5];
    float* out = (float*)d_out;

    __half *p_h0, *p_h1, *p_h2;
    cudaGetSymbolAddress((void**)&p_h0, g_h0);
    cudaGetSymbolAddress((void**)&p_h1, g_h1);
    cudaGetSymbolAddress((void**)&p_h2, g_h2);

    const int TPB = 256;

    const int SMEM1 = (128 * (IN_DIM + 8) + IN_DIM * (HIDDEN + 8)) * (int)sizeof(__half);
    const int SMEM2 = (128 * (HIDDEN + 8) + HIDDEN * (OUT_DIM + 8)) * (int)sizeof(__half);
    cudaFuncSetAttribute(gemm_tc_kernel<IN_DIM, HIDDEN, true>,
                         cudaFuncAttributeMaxDynamicSharedMemorySize, SMEM1);
    cudaFuncSetAttribute(gemm_tc_kernel<HIDDEN, OUT_DIM, false>,
                         cudaFuncAttributeMaxDynamicSharedMemorySize, SMEM2);

    const int GBLK = (N_NODES + 127) / 128;

    // Fork: gemm1 (x,w1 only) on a side stream, CSR build on the main stream.
    cudaStream_t s2;
    cudaEvent_t evFork, evJoin;
    cudaStreamCreateWithFlags(&s2, cudaStreamNonBlocking);
    cudaEventCreateWithFlags(&evFork, cudaEventDisableTiming);
    cudaEventCreateWithFlags(&evJoin, cudaEventDisableTiming);

    cudaEventRecord(evFork, 0);
    cudaStreamWaitEvent(s2, evFork, 0);
    gemm_tc_kernel<IN_DIM, HIDDEN, true><<<GBLK, 256, SMEM1, s2>>>(x, w1, p_h0, N_NODES);
    cudaEventRecord(evJoin, s2);

    // CSR build on the main stream (concurrent with gemm1).
    hist_kernel<<<(N_EDGES + TPB - 1) / TPB, TPB>>>(edge_dst);
    scan_lookback_kernel<<<SCAN_BLOCKS, 1024>>>();
    scatter_kernel<<<(N_EDGES + TPB - 1) / TPB, TPB>>>(edge_src, edge_dst, adj_vals);

    cudaStreamWaitEvent(0, evJoin, 0);

    // h1 = half(relu(A @ h0))
    spmm1_relu_kernel<<<(N_NODES * 32 + TPB - 1) / TPB, TPB>>>(p_h0, p_h1);
    // layer 2: h2 = half(h1 @ W2)
    gemm_tc_kernel<HIDDEN, OUT_DIM, false><<<GBLK, 256, SMEM2>>>(p_h1, w2, p_h2, N_NODES);
    // out = A @ h2
    spmm2_kernel<<<(N_NODES * 16 + TPB - 1) / TPB, TPB>>>(p_h2, out);

    cudaStreamCaptureStatus cap = cudaStreamCaptureStatusNone;
    cudaStreamIsCapturing(0, &cap);
    if (cap == cudaStreamCaptureStatusNone) {
        cudaStreamDestroy(s2);
        cudaEventDestroy(evFork);
        cudaEventDestroy(evJoin);
    }
}

// round 17
// speedup vs baseline: 1.3108x; 1.0128x over previous
#include <cuda_runtime.h>
#include <cuda_fp16.h>
#include <cstdint>

#define N_NODES 100000
#define N_EDGES 3200000
#define IN_DIM  256
#define HIDDEN  128
#define OUT_DIM 64

typedef unsigned long long ull;

#define SCAN_BLOCKS 98

// ---------------- device scratch (static; no cudaMalloc) ----------------
// invariant: g_cnt and g_scan_state are all-zero at kernel_launch entry
// (zero-initialized at module load; re-zeroed by scatter_kernel every call).
__device__ __align__(128) __half g_h0[(size_t)N_NODES * HIDDEN];  // X @ W1 (fp16)
__device__ __align__(128) __half g_h1[(size_t)N_NODES * HIDDEN];  // relu(A @ h0) (fp16)
__device__ __align__(128) __half g_h2[(size_t)N_NODES * OUT_DIM]; // h1 @ W2 (fp16)
__device__ int  g_cnt[N_NODES];
__device__ int  g_row_ptr[N_NODES + 1];
__device__ int  g_cursor[N_NODES];
__device__ ull  g_scan_state[SCAN_BLOCKS];                        // (sum<<2)|flag
__device__ __align__(128) int2 g_edges[N_EDGES];                  // {src, val bits}

// ---------------- helpers ----------------
__device__ __forceinline__ void pdl_wait() {
#if defined(__CUDA_ARCH__) && __CUDA_ARCH__ >= 900
    cudaGridDependencySynchronize();
#endif
}
__device__ __forceinline__ uint32_t smem_u32(const void* p) {
    return (uint32_t)__cvta_generic_to_shared(p);
}
__device__ __forceinline__ void ldmatrix_x4(uint32_t& r0, uint32_t& r1, uint32_t& r2,
                                            uint32_t& r3, uint32_t addr) {
    asm volatile("ldmatrix.sync.aligned.m8n8.x4.shared.b16 {%0,%1,%2,%3}, [%4];"
                 : "=r"(r0), "=r"(r1), "=r"(r2), "=r"(r3) : "r"(addr));
}
__device__ __forceinline__ void ldmatrix_x4_t(uint32_t& r0, uint32_t& r1, uint32_t& r2,
                                              uint32_t& r3, uint32_t addr) {
    asm volatile("ldmatrix.sync.aligned.m8n8.x4.trans.shared.b16 {%0,%1,%2,%3}, [%4];"
                 : "=r"(r0), "=r"(r1), "=r"(r2), "=r"(r3) : "r"(addr));
}
__device__ __forceinline__ void mma16816(float* d, const uint32_t* a, const uint32_t* b) {
    asm volatile("mma.sync.aligned.m16n8k16.row.col.f32.f16.f16.f32 "
                 "{%0,%1,%2,%3}, {%4,%5,%6,%7}, {%8,%9}, {%0,%1,%2,%3};"
                 : "+f"(d[0]), "+f"(d[1]), "+f"(d[2]), "+f"(d[3])
                 : "r"(a[0]), "r"(a[1]), "r"(a[2]), "r"(a[3]), "r"(b[0]), "r"(b[1]));
}
__device__ __forceinline__ uint32_t h2bits(__half2 h) {
    return *reinterpret_cast<uint32_t*>(&h);
}

// ---------------- CSR build ----------------
__global__ void hist_kernel(const int* __restrict__ edge_dst) {
    int e = blockIdx.x * blockDim.x + threadIdx.x;
    if (e < N_EDGES) atomicAdd(&g_cnt[edge_dst[e]], 1);
}

__device__ __forceinline__ int warp_incl_scan(int v) {
    int lane = threadIdx.x & 31;
    #pragma unroll
    for (int o = 1; o < 32; o <<= 1) {
        int n = __shfl_up_sync(0xffffffffu, v, o);
        if (lane >= o) v += n;
    }
    return v;
}

// single-pass decoupled-lookback exclusive scan: g_cnt -> g_row_ptr, g_cursor
// PDL consumer of hist.
__global__ __launch_bounds__(1024)
void scan_lookback_kernel() {
    pdl_wait();   // g_cnt must be final
    __shared__ int ws[32];
    __shared__ int s_prefix;
    const int bid = blockIdx.x;
    const int i = bid * 1024 + threadIdx.x;
    int v = (i < N_NODES) ? g_cnt[i] : 0;
    int incl = warp_incl_scan(v);
    int wid = threadIdx.x >> 5, lane = threadIdx.x & 31;
    if (lane == 31) ws[wid] = incl;
    __syncthreads();
    if (wid == 0) { int w = warp_incl_scan(ws[lane]); ws[lane] = w; }
    __syncthreads();
    int woff = (wid > 0) ? ws[wid - 1] : 0;
    int btotal = ws[31];

    if (threadIdx.x == 0) {
        ull pack = ((ull)(uint32_t)btotal << 2) | (bid == 0 ? 2u : 1u);
        atomicExch(&g_scan_state[bid], pack);
        int run = 0;
        if (bid > 0) {
            int idx = bid - 1;
            while (true) {
                ull s = atomicAdd(&g_scan_state[idx], 0ull);
                uint32_t flag = (uint32_t)(s & 3ull);
                if (flag == 0u) continue;
                run += (int)(s >> 2);
                if (flag == 2u) break;
                --idx;
            }
            atomicExch(&g_scan_state[bid],
                       ((ull)(uint32_t)(run + btotal) << 2) | 2u);
        }
        s_prefix = run;
    }
    __syncthreads();

    int ex = s_prefix + woff + incl - v;
    if (i < N_NODES) {
        g_row_ptr[i] = ex;
        g_cursor[i]  = ex;
    }
    if (bid == SCAN_BLOCKS - 1 && threadIdx.x == 1023)
        g_row_ptr[N_NODES] = N_EDGES;
}

// scatter (1 edge/thread) + restore zero-invariant. PDL consumer of scan.
__global__ void scatter_kernel(const int* __restrict__ edge_src,
                               const int* __restrict__ edge_dst,
                               const float* __restrict__ adj_vals) {
    int e = blockIdx.x * blockDim.x + threadIdx.x;
    pdl_wait();   // g_cursor must be ready; also orders the g_cnt re-zero after scan's reads
    if (e < N_NODES) g_cnt[e] = 0;
    if (e < SCAN_BLOCKS) g_scan_state[e] = 0ull;
    if (e >= N_EDGES) return;
    int d = edge_dst[e];
    int pos = atomicAdd(&g_cursor[d], 1);
    g_edges[pos] = make_int2(edge_src[e], __float_as_int(adj_vals[e]));
}

// ---------------- tensor-core GEMM: C[M,TN] = half(A[M,K] @ B_f32[K,TN]) ----------------
// If PDL: B (weights, independent) is staged BEFORE the grid-dependency sync;
// A (produced by the previous kernel) is staged after.
template<int K_DIM, int TN, bool A_IS_F32, bool PDL>
__global__ __launch_bounds__(256)
void gemm_tc_kernel(const void* __restrict__ Ain, const float* __restrict__ Bf,
                    __half* __restrict__ C, int M) {
    extern __shared__ __half sm[];
    constexpr int AP = K_DIM + 8;
    constexpr int BP = TN + 8;
    __half* As = sm;                       // [128][AP]
    __half* Bs = sm + 128 * AP;            // [K_DIM][BP]

    const int t = threadIdx.x;
    const int row0 = blockIdx.x * 128;

    // stage B (independent of producer)
    #pragma unroll
    for (int i = t; i < K_DIM * TN / 4; i += 256) {
        int k  = i / (TN / 4);
        int n4 = i % (TN / 4);
        float4 v = __ldg((const float4*)(Bf + (size_t)k * TN + n4 * 4));
        uint2 o = make_uint2(h2bits(__floats2half2_rn(v.x, v.y)),
                             h2bits(__floats2half2_rn(v.z, v.w)));
        *reinterpret_cast<uint2*>(Bs + k * BP + n4 * 4) = o;
    }
    if (PDL) pdl_wait();   // A (h1) becomes valid here
    if (A_IS_F32) {
        const float* A = (const float*)Ain;
        #pragma unroll
        for (int i = t; i < 128 * K_DIM / 4; i += 256) {
            int m  = i / (K_DIM / 4);
            int k4 = i % (K_DIM / 4);
            int gr = row0 + m;
            float4 v = make_float4(0.f, 0.f, 0.f, 0.f);
            if (gr < M) v = __ldg((const float4*)(A + (size_t)gr * K_DIM + k4 * 4));
            uint2 o = make_uint2(h2bits(__floats2half2_rn(v.x, v.y)),
                                 h2bits(__floats2half2_rn(v.z, v.w)));
            *reinterpret_cast<uint2*>(As + m * AP + k4 * 4) = o;
        }
    } else {
        const __half* A = (const __half*)Ain;
        #pragma unroll
        for (int i = t; i < 128 * K_DIM / 8; i += 256) {
            int m  = i / (K_DIM / 8);
            int k8 = i % (K_DIM / 8);
            int gr = row0 + m;
            uint4 v = make_uint4(0u, 0u, 0u, 0u);
            if (gr < M) v = __ldg((const uint4*)(A + (size_t)gr * K_DIM + k8 * 8));
            *reinterpret_cast<uint4*>(As + m * AP + k8 * 8) = v;
        }
    }
    __syncthreads();

    const int wid  = t >> 5;
    const int lane = t & 31;
    const int wm = wid & 3;
    const int wn = wid >> 2;
    const int m_base = wm * 32;
    const int n_base = wn * (TN / 2);
    constexpr int NTILES = TN / 2 / 8;

    float acc[2][NTILES][4];
    #pragma unroll
    for (int i = 0; i < 2; ++i)
        #pragma unroll
        for (int j = 0; j < NTILES; ++j)
            #pragma unroll
            for (int q = 0; q < 4; ++q) acc[i][j][q] = 0.f;

    const int a_row_off = lane & 15;
    const int a_col_off = (lane >> 4) * 8;
    const int b_krow = (lane & 7) + ((lane >> 3) & 1) * 8;
    const int b_ncol = (lane >> 4) * 8;

    #pragma unroll
    for (int ks = 0; ks < K_DIM / 16; ++ks) {
        const int k0 = ks * 16;
        uint32_t afrag[2][4];
        #pragma unroll
        for (int i = 0; i < 2; ++i) {
            int r = m_base + i * 16 + a_row_off;
            uint32_t addr = smem_u32(As + r * AP + k0 + a_col_off);
            ldmatrix_x4(afrag[i][0], afrag[i][1], afrag[i][2], afrag[i][3], addr);
        }
        uint32_t bfrag[NTILES][2];
        #pragma unroll
        for (int j = 0; j < NTILES / 2; ++j) {
            int kr = k0 + b_krow;
            int nc = n_base + j * 16 + b_ncol;
            uint32_t addr = smem_u32(Bs + kr * BP + nc);
            ldmatrix_x4_t(bfrag[2 * j][0], bfrag[2 * j][1],
                          bfrag[2 * j + 1][0], bfrag[2 * j + 1][1], addr);
        }
        #pragma unroll
        for (int i = 0; i < 2; ++i)
            #pragma unroll
            for (int j = 0; j < NTILES; ++j)
                mma16816(acc[i][j], afrag[i], bfrag[j]);
    }

    const int erow = lane >> 2;
    const int ecol = (lane & 3) * 2;
    #pragma unroll
    for (int i = 0; i < 2; ++i) {
        int r0 = row0 + m_base + i * 16 + erow;
        #pragma unroll
        for (int j = 0; j < NTILES; ++j) {
            int col = n_base + j * 8 + ecol;
            if (r0 < M) {
                __half2 h = __floats2half2_rn(acc[i][j][0], acc[i][j][1]);
                *reinterpret_cast<uint32_t*>(C + (size_t)r0 * TN + col) = h2bits(h);
            }
            if (r0 + 8 < M) {
                __half2 h = __floats2half2_rn(acc[i][j][2], acc[i][j][3]);
                *reinterpret_cast<uint32_t*>(C + (size_t)(r0 + 8) * TN + col) = h2bits(h);
            }
        }
    }
}

// ---------------- spmm1: h1 = relu(A @ h0_fp16), fp16 out; warp-per-row ----------------
// Paired edge loads: one broadcast int4 = two edges. (Plain launch: dual dependency.)
__global__ void spmm1_relu_kernel(const __half* __restrict__ h0, __half* __restrict__ h1) {
    int row = (int)((blockIdx.x * blockDim.x + threadIdx.x) >> 5);
    if (row >= N_NODES) return;
    int lane = threadIdx.x & 31;
    int beg = g_row_ptr[row];
    int end = g_row_ptr[row + 1];
    int c = lane * 4;
    float4 acc = make_float4(0.f, 0.f, 0.f, 0.f);

    int e = beg;
    if ((e & 1) && e < end) {
        int2 d0 = __ldg(&g_edges[e]);
        float v0 = __int_as_float(d0.y);
        uint2 r0 = __ldg((const uint2*)(h0 + ((size_t)d0.x << 7) + c));
        float2 a0 = __half22float2(*reinterpret_cast<__half2*>(&r0.x));
        float2 b0 = __half22float2(*reinterpret_cast<__half2*>(&r0.y));
        acc.x = fmaf(v0, a0.x, acc.x); acc.y = fmaf(v0, a0.y, acc.y);
        acc.z = fmaf(v0, b0.x, acc.z); acc.w = fmaf(v0, b0.y, acc.w);
        ++e;
    }
    for (; e + 3 < end; e += 4) {
        int4 p0 = __ldg((const int4*)(g_edges + e));
        int4 p1 = __ldg((const int4*)(g_edges + e + 2));
        uint2 r0 = __ldg((const uint2*)(h0 + ((size_t)p0.x << 7) + c));
        uint2 r1 = __ldg((const uint2*)(h0 + ((size_t)p0.z << 7) + c));
        uint2 r2 = __ldg((const uint2*)(h0 + ((size_t)p1.x << 7) + c));
        uint2 r3 = __ldg((const uint2*)(h0 + ((size_t)p1.z << 7) + c));
        float v0 = __int_as_float(p0.y), v1 = __int_as_float(p0.w);
        float v2 = __int_as_float(p1.y), v3 = __int_as_float(p1.w);
        float2 a0 = __half22float2(*reinterpret_cast<__half2*>(&r0.x));
        float2 b0 = __half22float2(*reinterpret_cast<__half2*>(&r0.y));
        float2 a1 = __half22float2(*reinterpret_cast<__half2*>(&r1.x));
        float2 b1 = __half22float2(*reinterpret_cast<__half2*>(&r1.y));
        float2 a2 = __half22float2(*reinterpret_cast<__half2*>(&r2.x));
        float2 b2 = __half22float2(*reinterpret_cast<__half2*>(&r2.y));
        float2 a3 = __half22float2(*reinterpret_cast<__half2*>(&r3.x));
        float2 b3 = __half22float2(*reinterpret_cast<__half2*>(&r3.y));
        acc.x = fmaf(v0, a0.x, acc.x); acc.y = fmaf(v0, a0.y, acc.y);
        acc.z = fmaf(v0, b0.x, acc.z); acc.w = fmaf(v0, b0.y, acc.w);
        acc.x = fmaf(v1, a1.x, acc.x); acc.y = fmaf(v1, a1.y, acc.y);
        acc.z = fmaf(v1, b1.x, acc.z); acc.w = fmaf(v1, b1.y, acc.w);
        acc.x = fmaf(v2, a2.x, acc.x); acc.y = fmaf(v2, a2.y, acc.y);
        acc.z = fmaf(v2, b2.x, acc.z); acc.w = fmaf(v2, b2.y, acc.w);
        acc.x = fmaf(v3, a3.x, acc.x); acc.y = fmaf(v3, a3.y, acc.y);
        acc.z = fmaf(v3, b3.x, acc.z); acc.w = fmaf(v3, b3.y, acc.w);
    }
    for (; e < end; ++e) {
        int2 d0 = __ldg(&g_edges[e]);
        float v0 = __int_as_float(d0.y);
        uint2 r0 = __ldg((const uint2*)(h0 + ((size_t)d0.x << 7) + c));
        float2 a0 = __half22float2(*reinterpret_cast<__half2*>(&r0.x));
        float2 b0 = __half22float2(*reinterpret_cast<__half2*>(&r0.y));
        acc.x = fmaf(v0, a0.x, acc.x); acc.y = fmaf(v0, a0.y, acc.y);
        acc.z = fmaf(v0, b0.x, acc.z); acc.w = fmaf(v0, b0.y, acc.w);
    }
    __half2 o0 = __floats2half2_rn(fmaxf(acc.x, 0.f), fmaxf(acc.y, 0.f));
    __half2 o1 = __floats2half2_rn(fmaxf(acc.z, 0.f), fmaxf(acc.w, 0.f));
    uint2 ov = make_uint2(h2bits(o0), h2bits(o1));
    *reinterpret_cast<uint2*>(h1 + ((size_t)row << 7) + c) = ov;
}

// ---------------- spmm2: out = A @ h2_fp16 (fp32 out); half-warp per row ----------------
// PDL consumer of gemm2: row_ptr read happens pre-sync; h2 gathers after.
__global__ void spmm2_kernel(const __half* __restrict__ h2, float* __restrict__ out) {
    int gt = blockIdx.x * blockDim.x + threadIdx.x;
    int row = gt >> 4;
    if (row >= N_NODES) { pdl_wait(); return; }
    int lane16 = threadIdx.x & 15;
    int beg = g_row_ptr[row];        // independent of gemm2
    int end = g_row_ptr[row + 1];
    int c = lane16 * 4;
    float4 acc = make_float4(0.f, 0.f, 0.f, 0.f);

    pdl_wait();                      // h2 becomes valid here

    int e = beg;
    if ((e & 1) && e < end) {
        int2 d0 = __ldg(&g_edges[e]);
        float v0 = __int_as_float(d0.y);
        uint2 r0 = __ldg((const uint2*)(h2 + ((size_t)d0.x << 6) + c));
        float2 a0 = __half22float2(*reinterpret_cast<__half2*>(&r0.x));
        float2 b0 = __half22float2(*reinterpret_cast<__half2*>(&r0.y));
        acc.x = fmaf(v0, a0.x, acc.x); acc.y = fmaf(v0, a0.y, acc.y);
        acc.z = fmaf(v0, b0.x, acc.z); acc.w = fmaf(v0, b0.y, acc.w);
        ++e;
    }
    for (; e + 3 < end; e += 4) {
        int4 p0 = __ldg((const int4*)(g_edges + e));
        int4 p1 = __ldg((const int4*)(g_edges + e + 2));
        uint2 r0 = __ldg((const uint2*)(h2 + ((size_t)p0.x << 6) + c));
        uint2 r1 = __ldg((const uint2*)(h2 + ((size_t)p0.z << 6) + c));
        uint2 r2 = __ldg((const uint2*)(h2 + ((size_t)p1.x << 6) + c));
        uint2 r3 = __ldg((const uint2*)(h2 + ((size_t)p1.z << 6) + c));
        float v0 = __int_as_float(p0.y), v1 = __int_as_float(p0.w);
        float v2 = __int_as_float(p1.y), v3 = __int_as_float(p1.w);
        float2 a0 = __half22float2(*reinterpret_cast<__half2*>(&r0.x));
        float2 b0 = __half22float2(*reinterpret_cast<__half2*>(&r0.y));
        float2 a1 = __half22float2(*reinterpret_cast<__half2*>(&r1.x));
        float2 b1 = __half22float2(*reinterpret_cast<__half2*>(&r1.y));
        float2 a2 = __half22float2(*reinterpret_cast<__half2*>(&r2.x));
        float2 b2 = __half22float2(*reinterpret_cast<__half2*>(&r2.y));
        float2 a3 = __half22float2(*reinterpret_cast<__half2*>(&r3.x));
        float2 b3 = __half22float2(*reinterpret_cast<__half2*>(&r3.y));
        acc.x = fmaf(v0, a0.x, acc.x); acc.y = fmaf(v0, a0.y, acc.y);
        acc.z = fmaf(v0, b0.x, acc.z); acc.w = fmaf(v0, b0.y, acc.w);
        acc.x = fmaf(v1, a1.x, acc.x); acc.y = fmaf(v1, a1.y, acc.y);
        acc.z = fmaf(v1, b1.x, acc.z); acc.w = fmaf(v1, b1.y, acc.w);
        acc.x = fmaf(v2, a2.x, acc.x); acc.y = fmaf(v2, a2.y, acc.y);
        acc.z = fmaf(v2, b2.x, acc.z); acc.w = fmaf(v2, b2.y, acc.w);
        acc.x = fmaf(v3, a3.x, acc.x); acc.y = fmaf(v3, a3.y, acc.y);
        acc.z = fmaf(v3, b3.x, acc.z); acc.w = fmaf(v3, b3.y, acc.w);
    }
    for (; e < end; ++e) {
        int2 d0 = __ldg(&g_edges[e]);
        float v0 = __int_as_float(d0.y);
        uint2 r0 = __ldg((const uint2*)(h2 + ((size_t)d0.x << 6) + c));
        float2 a0 = __half22float2(*reinterpret_cast<__half2*>(&r0.x));
        float2 b0 = __half22float2(*reinterpret_cast<__half2*>(&r0.y));
        acc.x = fmaf(v0, a0.x, acc.x); acc.y = fmaf(v0, a0.y, acc.y);
        acc.z = fmaf(v0, b0.x, acc.z); acc.w = fmaf(v0, b0.y, acc.w);
    }
    *reinterpret_cast<float4*>(out + ((size_t)row << 6) + c) = acc;
}

// ---------------- PDL launch helper ----------------
template <typename K, typename... Args>
static void launch_pdl(K kernel, dim3 grid, dim3 block, size_t smem,
                       cudaStream_t stream, Args... args) {
    cudaLaunchConfig_t cfg = {};
    cfg.gridDim = grid;
    cfg.blockDim = block;
    cfg.dynamicSmemBytes = smem;
    cfg.stream = stream;
    cudaLaunchAttribute attr[1];
    attr[0].id = cudaLaunchAttributeProgrammaticStreamSerialization;
    attr[0].val.programmaticStreamSerializationAllowed = 1;
    cfg.attrs = attr;
    cfg.numAttrs = 1;
    cudaLaunchKernelEx(&cfg, kernel, args...);
}

// ---------------- launch ----------------
extern "C" void kernel_launch(void* const* d_in, const int* in_sizes, int n_in,
                              void* d_out, int out_size) {
    const float* x        = (const float*)d_in[0];
    const float* adj_vals = (const float*)d_in[1];
    const float* w1       = (const float*)d_in[2];
    const float* w2       = (const float*)d_in[3];
    const int*   edge_src = (const int*)d_in[4];
    const int*   edge_dst = (const int*)d_in[5];
    float* out = (float*)d_out;

    __half *p_h0, *p_h1, *p_h2;
    cudaGetSymbolAddress((void**)&p_h0, g_h0);
    cudaGetSymbolAddress((void**)&p_h1, g_h1);
    cudaGetSymbolAddress((void**)&p_h2, g_h2);

    const int TPB = 256;

    const int SMEM1 = (128 * (IN_DIM + 8) + IN_DIM * (HIDDEN + 8)) * (int)sizeof(__half);
    const int SMEM2 = (128 * (HIDDEN + 8) + HIDDEN * (OUT_DIM + 8)) * (int)sizeof(__half);
    cudaFuncSetAttribute(gemm_tc_kernel<IN_DIM, HIDDEN, true, false>,
                         cudaFuncAttributeMaxDynamicSharedMemorySize, SMEM1);
    cudaFuncSetAttribute(gemm_tc_kernel<HIDDEN, OUT_DIM, false, true>,
                         cudaFuncAttributeMaxDynamicSharedMemorySize, SMEM2);

    const int GBLK = (N_NODES + 127) / 128;

    // Fork: gemm1 (x,w1 only) on a side stream, CSR build on the main stream.
    cudaStream_t s2;
    cudaEvent_t evFork, evJoin;
    cudaStreamCreateWithFlags(&s2, cudaStreamNonBlocking);
    cudaEventCreateWithFlags(&evFork, cudaEventDisableTiming);
    cudaEventCreateWithFlags(&evJoin, cudaEventDisableTiming);

    cudaEventRecord(evFork, 0);
    cudaStreamWaitEvent(s2, evFork, 0);
    gemm_tc_kernel<IN_DIM, HIDDEN, true, false><<<GBLK, 256, SMEM1, s2>>>(x, w1, p_h0, N_NODES);
    cudaEventRecord(evJoin, s2);

    // CSR build on the main stream (concurrent with gemm1); PDL on the chain edges.
    hist_kernel<<<(N_EDGES + TPB - 1) / TPB, TPB>>>(edge_dst);
    launch_pdl(scan_lookback_kernel, dim3(SCAN_BLOCKS), dim3(1024), 0, (cudaStream_t)0);
    launch_pdl(scatter_kernel, dim3((N_EDGES + TPB - 1) / TPB), dim3(TPB), 0,
               (cudaStream_t)0, edge_src, edge_dst, adj_vals);

    cudaStreamWaitEvent(0, evJoin, 0);

    // h1 = half(relu(A @ h0))  (plain launch: dual dependency)
    spmm1_relu_kernel<<<(N_NODES * 32 + TPB - 1) / TPB, TPB>>>(p_h0, p_h1);
    // layer 2: h2 = half(h1 @ W2)  (PDL: stages W2 under spmm1's drain)
    launch_pdl(gemm_tc_kernel<HIDDEN, OUT_DIM, false, true>, dim3(GBLK), dim3(256),
               (size_t)SMEM2, (cudaStream_t)0, (const void*)p_h1, w2, p_h2, (int)N_NODES);
    // out = A @ h2  (PDL: row_ptr/edge setup under gemm2's drain)
    launch_pdl(spmm2_kernel, dim3((N_NODES * 16 + TPB - 1) / TPB), dim3(TPB), 0,
               (cudaStream_t)0, (const __half*)p_h2, out);

    cudaStreamCaptureStatus cap = cudaStreamCaptureStatusNone;
    cudaStreamIsCapturing(0, &cap);
    if (cap == cudaStreamCaptureStatusNone) {
        cudaStreamDestroy(s2);
        cudaEventDestroy(evFork);
        cudaEventDestroy(evJoin);
    }
}